// round 3
// baseline (speedup 1.0000x reference)
#include <cuda_runtime.h>
#include <cstdint>
#include <cstddef>

#define B_ 256
#define S_ 512
#define H_ 512
#define V_ 128

// Scratch (allocation-free rule: __device__ globals)
__device__ float g_P[V_ * H_];                       // 256 KB: P[v][h] = emb[v]@W_ih + b_ih + b_hh
__device__ float g_H[(size_t)S_ * B_ * H_];          // 268 MB: hidden states, layout [t][b][h]

// ---- packed f32x2 helpers (sm_103a) ----
__device__ __forceinline__ unsigned long long pack2(float x, float y) {
    unsigned long long r;
    asm("mov.b64 %0, {%1, %2};" : "=l"(r) : "f"(x), "f"(y));
    return r;
}
__device__ __forceinline__ void unpack2(unsigned long long v, float& x, float& y) {
    asm("mov.b64 {%0, %1}, %2;" : "=f"(x), "=f"(y) : "l"(v));
}
#define FMA2(acc, a, b) \
    asm("fma.rn.f32x2 %0, %1, %2, %3;" : "=l"(acc) : "l"(a), "l"(b), "l"(acc))

// ============================================================
// Kernel 1: P[v][h] = sum_k emb[v][k] * W_ih[k][h] + b_ih[h] + b_hh[h]
// grid = 128 blocks (one per vocab id), 512 threads (one per h)
// ============================================================
__global__ void precompute_P(const float* __restrict__ emb,
                             const float* __restrict__ W_ih,
                             const float* __restrict__ b_ih,
                             const float* __restrict__ b_hh) {
    __shared__ float es[H_];
    const int v = blockIdx.x;
    const int h = threadIdx.x;
    es[h] = emb[v * H_ + h];
    __syncthreads();
    float acc = b_ih[h] + b_hh[h];
#pragma unroll 4
    for (int k = 0; k < H_; k++)
        acc = fmaf(es[k], W_ih[k * H_ + h], acc);
    g_P[v * H_ + h] = acc;
}

// ============================================================
// Kernel 2: one recurrence step.
//   g_H[t][b][n] = tanh( sum_k g_H[t-1][b][k] * W_hh[k][n] + P[x[b][t]][n] )
// grid = (8 col-tiles of 64, 16 row-tiles of 16) = 128 CTAs, 256 threads.
// h_prev is staged into SMEM as duplicated {h,h} u64 pairs so the inner
// loop is LDS.64(broadcast) + LDG.128(W pair) + 2x fma.rn.f32x2.
// Dynamic SMEM: 16 * 512 * 8 = 64 KB.
// ============================================================
__global__ void rnn_step(const float* __restrict__ Whh,
                         const int* __restrict__ x,
                         int t) {
    extern __shared__ unsigned long long hh_s[];   // [16][512] duplicated pairs
    const int tid = threadIdx.x;
    const int bx = blockIdx.x;    // col tile  0..7   (64 cols each)
    const int by = blockIdx.y;    // row tile  0..15  (16 batch rows each)

    if (t > 0) {
        // stage h_prev tile: 16 rows x 512 floats = 2048 float4 loads
        const float4* src = (const float4*)(g_H + (size_t)(t - 1) * (B_ * H_)
                                                + (size_t)by * 16 * H_);
#pragma unroll
        for (int it = 0; it < 8; it++) {
            int i = tid + it * 256;          // 0..2047
            float4 v = src[i];
            unsigned long long* d = hh_s + (size_t)i * 4;
            d[0] = pack2(v.x, v.x);
            d[1] = pack2(v.y, v.y);
            d[2] = pack2(v.z, v.z);
            d[3] = pack2(v.w, v.w);
        }
    }
    __syncthreads();

    const int r   = tid >> 4;           // 0..15 row within tile
    const int c4  = tid & 15;           // 0..15 col quad
    const int b   = by * 16 + r;
    const int col = bx * 64 + c4 * 4;

    unsigned long long a0 = 0ull, a1 = 0ull;   // {0.f,0.f} packed

    if (t > 0) {
        const ulonglong2* wp = (const ulonglong2*)(Whh + col);   // 16B aligned (col % 4 == 0)
        const unsigned long long* hp = hh_s + (size_t)r * H_;
#pragma unroll 8
        for (int k = 0; k < H_; k++) {
            unsigned long long hh = hp[k];
            ulonglong2 w = wp[(size_t)k * (H_ / 4)];   // row k, 4 floats = 2 pairs
            FMA2(a0, hh, w.x);
            FMA2(a1, hh, w.y);
        }
    }

    const int xv = x[b * S_ + t];
    const float4 p = *(const float4*)(g_P + (size_t)xv * H_ + col);

    float f0, f1, f2, f3;
    unpack2(a0, f0, f1);
    unpack2(a1, f2, f3);
    float4 o;
    o.x = tanhf(f0 + p.x);
    o.y = tanhf(f1 + p.y);
    o.z = tanhf(f2 + p.z);
    o.w = tanhf(f3 + p.w);
    *(float4*)(g_H + (size_t)t * (B_ * H_) + (size_t)b * H_ + col) = o;
}

// ============================================================
// Kernel 3: output projection.
//   out[b][s][v] = sum_k g_H[s][b][k] * W_ho[k][v] + b_o[v]
// Flattened rows r = s*256 + b (M = 131072), N = 128, K = 512.
// grid = (1024 row-blocks of 128, 2 col-blocks of 64), 256 threads.
// Thread tile 4 rows x 8 cols via f32x2. SMEM tiles BK = 16.
// ============================================================
__global__ __launch_bounds__(256) void out_gemm(const float* __restrict__ Who,
                                                const float* __restrict__ b_o,
                                                float* __restrict__ out) {
    __shared__ unsigned long long Hs[128 * 16];  // duplicated pairs, 16 KB
    __shared__ float Ws[16 * 64];                // 4 KB

    const int tid = threadIdx.x;
    const int rb  = blockIdx.x;      // row block
    const int cb  = blockIdx.y;      // col block (0..1)
    const int tx  = tid & 7;         // 8 col groups of 8 cols
    const int ty  = tid >> 3;        // 32 row groups of 4 rows

    unsigned long long acc[4][4];
#pragma unroll
    for (int i = 0; i < 4; i++)
#pragma unroll
        for (int j = 0; j < 4; j++) acc[i][j] = 0ull;

    const float* Hbase = g_H + (size_t)rb * 128 * H_;

    for (int k0 = 0; k0 < H_; k0 += 16) {
        __syncthreads();   // protect SMEM reuse from previous iteration
        // stage Hs: 128 rows x 16 floats = 512 float4
#pragma unroll
        for (int it = 0; it < 2; it++) {
            int fi = tid + it * 256;          // 0..511
            int row = fi >> 2, part = fi & 3;
            float4 v = *(const float4*)(Hbase + (size_t)row * H_ + k0 + part * 4);
            unsigned long long* d = Hs + row * 16 + part * 4;
            d[0] = pack2(v.x, v.x);
            d[1] = pack2(v.y, v.y);
            d[2] = pack2(v.z, v.z);
            d[3] = pack2(v.w, v.w);
        }
        // stage Ws: 16 k-rows x 64 cols = 256 float4
        {
            int fi = tid;                      // 0..255
            int kk = fi >> 4, part = fi & 15;
            float4 v = *(const float4*)(Who + (size_t)(k0 + kk) * V_ + cb * 64 + part * 4);
            *(float4*)(Ws + kk * 64 + part * 4) = v;
        }
        __syncthreads();

#pragma unroll
        for (int k = 0; k < 16; k++) {
            unsigned long long h0 = Hs[(ty * 4 + 0) * 16 + k];
            unsigned long long h1 = Hs[(ty * 4 + 1) * 16 + k];
            unsigned long long h2 = Hs[(ty * 4 + 2) * 16 + k];
            unsigned long long h3 = Hs[(ty * 4 + 3) * 16 + k];
            ulonglong2 w0 = *(const ulonglong2*)&Ws[k * 64 + tx * 8];
            ulonglong2 w1 = *(const ulonglong2*)&Ws[k * 64 + tx * 8 + 4];
            FMA2(acc[0][0], h0, w0.x); FMA2(acc[0][1], h0, w0.y);
            FMA2(acc[0][2], h0, w1.x); FMA2(acc[0][3], h0, w1.y);
            FMA2(acc[1][0], h1, w0.x); FMA2(acc[1][1], h1, w0.y);
            FMA2(acc[1][2], h1, w1.x); FMA2(acc[1][3], h1, w1.y);
            FMA2(acc[2][0], h2, w0.x); FMA2(acc[2][1], h2, w0.y);
            FMA2(acc[2][2], h2, w1.x); FMA2(acc[2][3], h2, w1.y);
            FMA2(acc[3][0], h3, w0.x); FMA2(acc[3][1], h3, w0.y);
            FMA2(acc[3][2], h3, w1.x); FMA2(acc[3][3], h3, w1.y);
        }
    }

    float bo[8];
#pragma unroll
    for (int c = 0; c < 8; c++) bo[c] = b_o[cb * 64 + tx * 8 + c];

#pragma unroll
    for (int i = 0; i < 4; i++) {
        int r = rb * 128 + ty * 4 + i;     // flat index = s*256 + b
        int s = r >> 8;
        int b = r & 255;
        float* dst = out + ((size_t)b * S_ + s) * V_ + cb * 64 + tx * 8;
        float f[8];
        unpack2(acc[i][0], f[0], f[1]);
        unpack2(acc[i][1], f[2], f[3]);
        unpack2(acc[i][2], f[4], f[5]);
        unpack2(acc[i][3], f[6], f[7]);
        float4 o0 = make_float4(f[0] + bo[0], f[1] + bo[1], f[2] + bo[2], f[3] + bo[3]);
        float4 o1 = make_float4(f[4] + bo[4], f[5] + bo[5], f[6] + bo[6], f[7] + bo[7]);
        *(float4*)dst = o0;
        *((float4*)dst + 1) = o1;
    }
}

// ============================================================
// Kernel 4: hT = g_H[S-1]  (appended after outputs in d_out)
// ============================================================
__global__ void copy_hT(float* __restrict__ out) {
    int i = blockIdx.x * blockDim.x + threadIdx.x;   // 0 .. B_*H_-1
    out[(size_t)B_ * S_ * V_ + i] = g_H[(size_t)(S_ - 1) * (B_ * H_) + i];
}

// ============================================================
extern "C" void kernel_launch(void* const* d_in, const int* in_sizes, int n_in,
                              void* d_out, int out_size) {
    const int*   x    = (const int*)d_in[0];
    const float* emb  = (const float*)d_in[1];
    const float* W_ih = (const float*)d_in[2];
    const float* b_ih = (const float*)d_in[3];
    const float* W_hh = (const float*)d_in[4];
    const float* b_hh = (const float*)d_in[5];
    const float* W_ho = (const float*)d_in[6];
    const float* b_o  = (const float*)d_in[7];
    float* out = (float*)d_out;

    cudaFuncSetAttribute(rnn_step, cudaFuncAttributeMaxDynamicSharedMemorySize, 65536);

    precompute_P<<<V_, H_>>>(emb, W_ih, b_ih, b_hh);

    for (int t = 0; t < S_; t++)
        rnn_step<<<dim3(8, 16), 256, 65536>>>(W_hh, x, t);

    out_gemm<<<dim3((B_ * S_) / 128, V_ / 64), 256>>>(W_ho, b_o, out);

    if ((long long)out_size >= (long long)B_ * S_ * V_ + (long long)B_ * H_)
        copy_hT<<<(B_ * H_) / 256, 256>>>(out);
}

// round 7
// speedup vs baseline: 2.3340x; 2.3340x over previous
#include <cuda_runtime.h>
#include <cstdint>
#include <cstddef>

#define B_ 256
#define S_ 512
#define H_ 512
#define V_ 128

// Scratch (allocation-free rule: __device__ globals)
__device__ float g_P[V_ * H_];                       // 256 KB: P[v][h] = emb[v]@W_ih + b_ih + b_hh
__device__ float g_H[(size_t)S_ * B_ * H_];          // 268 MB: hidden states, layout [t][b][h]
__device__ unsigned g_cnt;                           // grid-barrier arrive counter (always returns to 0)
__device__ unsigned g_epoch;                         // grid-barrier release epoch (monotonic across replays)

// ---- packed f32x2 helpers (sm_103a) ----
__device__ __forceinline__ unsigned long long pack2(float x, float y) {
    unsigned long long r;
    asm("mov.b64 %0, {%1, %2};" : "=l"(r) : "f"(x), "f"(y));
    return r;
}
__device__ __forceinline__ void unpack2(unsigned long long v, float& x, float& y) {
    asm("mov.b64 {%0, %1}, %2;" : "=f"(x), "=f"(y) : "l"(v));
}
#define FMA2(acc, a, b) \
    asm("fma.rn.f32x2 %0, %1, %2, %3;" : "=l"(acc) : "l"(a), "l"(b), "l"(acc))

// ============================================================
// Kernel 1: P[v][h] = sum_k emb[v][k] * W_ih[k][h] + b_ih[h] + b_hh[h]
// ============================================================
__global__ void precompute_P(const float* __restrict__ emb,
                             const float* __restrict__ W_ih,
                             const float* __restrict__ b_ih,
                             const float* __restrict__ b_hh) {
    __shared__ float es[H_];
    const int v = blockIdx.x;
    const int h = threadIdx.x;
    es[h] = emb[v * H_ + h];
    __syncthreads();
    float acc = b_ih[h] + b_hh[h];
#pragma unroll 4
    for (int k = 0; k < H_; k++)
        acc = fmaf(es[k], W_ih[k * H_ + h], acc);
    g_P[v * H_ + h] = acc;
}

// ============================================================
// Kernel 2: PERSISTENT recurrence — all 512 steps in one launch.
// grid = (8 col-tiles of 64, 16 row-tiles of 16) = 128 CTAs, 256 threads.
// 1 CTA/SM (196KB SMEM), 128 <= 148 SMs => all CTAs co-resident in wave 1,
// so a software grid barrier is safe.
//
// SMEM: Ws[512][64] float  = 128KB  (this CTA's W_hh column slice, loaded once)
//       hs[16][513] u64    =  64KB  (h_prev tile as duplicated {h,h} pairs,
//                                    row stride 513 to avoid bank conflicts)
// Inner loop: LDS.64(h broadcast) + LDS.128(W pair) + 2x fma.rn.f32x2.
// ============================================================
#define HS_STRIDE 513

__global__ __launch_bounds__(256) void rnn_persist(const float* __restrict__ Whh,
                                                   const int* __restrict__ x) {
    extern __shared__ char smem_raw[];
    float* Ws = (float*)smem_raw;                                        // 512*64 floats
    unsigned long long* hs = (unsigned long long*)(smem_raw + 512 * 64 * 4);

    const int tid = threadIdx.x;
    const int bx = blockIdx.x;    // col tile 0..7   (64 cols)
    const int by = blockIdx.y;    // row tile 0..15  (16 batch rows)

    // ---- load this CTA's W_hh slice into SMEM (once) ----
#pragma unroll
    for (int it = 0; it < 32; it++) {
        int i = tid + it * 256;           // 0..8191 float4s
        int k = i >> 4;                   // 16 float4 per k-row
        int p = i & 15;
        float4 v = *(const float4*)(Whh + (size_t)k * H_ + bx * 64 + p * 4);
        *(float4*)(Ws + k * 64 + p * 4) = v;
    }

    unsigned e0 = 0;
    if (tid == 0) e0 = *(volatile unsigned*)&g_epoch;   // epoch base (replay-safe)
    __syncthreads();

    const int r   = tid >> 4;             // 0..15 row within tile
    const int c4  = tid & 15;             // 0..15 col quad
    const int b   = by * 16 + r;
    const int col = bx * 64 + c4 * 4;
    const unsigned long long* hp = hs + (size_t)r * HS_STRIDE;
    const ulonglong2* wp = (const ulonglong2*)(Ws + c4 * 4);  // stride per k = 16 ulonglong2

    for (int t = 0; t < S_; t++) {
        unsigned long long a0 = 0ull, a1 = 0ull;

        if (t > 0) {
            // stage h_prev tile from L2 (fresh addresses each step; bypass L1)
            const float4* src = (const float4*)(g_H + (size_t)(t - 1) * (B_ * H_)
                                                    + (size_t)by * 16 * H_);
#pragma unroll
            for (int it = 0; it < 8; it++) {
                int i = tid + it * 256;           // 0..2047 float4s
                int row = i >> 7;                 // 128 float4 per row
                int w4  = i & 127;
                float4 v = __ldcg(src + i);
                unsigned long long* d = hs + (size_t)row * HS_STRIDE + (size_t)w4 * 4;
                d[0] = pack2(v.x, v.x);
                d[1] = pack2(v.y, v.y);
                d[2] = pack2(v.z, v.z);
                d[3] = pack2(v.w, v.w);
            }
            __syncthreads();

#pragma unroll 8
            for (int k = 0; k < H_; k++) {
                unsigned long long hh = hp[k];
                ulonglong2 w = wp[(size_t)k * 16];
                FMA2(a0, hh, w.x);
                FMA2(a1, hh, w.y);
            }
        }

        const int xv = __ldg(&x[b * S_ + t]);
        const float4 p = *(const float4*)(g_P + (size_t)xv * H_ + col);

        float f0, f1, f2, f3;
        unpack2(a0, f0, f1);
        unpack2(a1, f2, f3);
        float4 o;
        o.x = tanhf(f0 + p.x);
        o.y = tanhf(f1 + p.y);
        o.z = tanhf(f2 + p.z);
        o.w = tanhf(f3 + p.w);
        *(float4*)(g_H + (size_t)t * (B_ * H_) + (size_t)b * H_ + col) = o;

        __syncthreads();   // all h writes issued; hs no longer being read
        // ---- software grid barrier ----
        if (tid == 0) {
            __threadfence();                                // h -> L2 visible before arrive
            unsigned old = atomicAdd(&g_cnt, 1);
            if (old == 127) {                               // last arriver
                atomicExch(&g_cnt, 0);                      // reset for next barrier
                __threadfence();
                atomicAdd(&g_epoch, 1);                     // release
            }
            while (*(volatile unsigned*)&g_epoch < e0 + (unsigned)(t + 1)) { }
        }
        __syncthreads();
    }
}

// ============================================================
// Kernel 3: output projection.
//   out[b][s][v] = sum_k g_H[s][b][k] * W_ho[k][v] + b_o[v]
// ============================================================
__global__ __launch_bounds__(256) void out_gemm(const float* __restrict__ Who,
                                                const float* __restrict__ b_o,
                                                float* __restrict__ out) {
    __shared__ unsigned long long Hs[128 * 16];  // duplicated pairs, 16 KB
    __shared__ float Ws[16 * 64];                // 4 KB

    const int tid = threadIdx.x;
    const int rb  = blockIdx.x;      // row block
    const int cb  = blockIdx.y;      // col block (0..1)
    const int tx  = tid & 7;         // 8 col groups of 8 cols
    const int ty  = tid >> 3;        // 32 row groups of 4 rows

    unsigned long long acc[4][4];
#pragma unroll
    for (int i = 0; i < 4; i++)
#pragma unroll
        for (int j = 0; j < 4; j++) acc[i][j] = 0ull;

    const float* Hbase = g_H + (size_t)rb * 128 * H_;

    for (int k0 = 0; k0 < H_; k0 += 16) {
        __syncthreads();
#pragma unroll
        for (int it = 0; it < 2; it++) {
            int fi = tid + it * 256;          // 0..511
            int row = fi >> 2, part = fi & 3;
            float4 v = *(const float4*)(Hbase + (size_t)row * H_ + k0 + part * 4);
            unsigned long long* d = Hs + row * 16 + part * 4;
            d[0] = pack2(v.x, v.x);
            d[1] = pack2(v.y, v.y);
            d[2] = pack2(v.z, v.z);
            d[3] = pack2(v.w, v.w);
        }
        {
            int fi = tid;                      // 0..255
            int kk = fi >> 4, part = fi & 15;
            float4 v = *(const float4*)(Who + (size_t)(k0 + kk) * V_ + cb * 64 + part * 4);
            *(float4*)(Ws + kk * 64 + part * 4) = v;
        }
        __syncthreads();

#pragma unroll
        for (int k = 0; k < 16; k++) {
            unsigned long long h0 = Hs[(ty * 4 + 0) * 16 + k];
            unsigned long long h1 = Hs[(ty * 4 + 1) * 16 + k];
            unsigned long long h2 = Hs[(ty * 4 + 2) * 16 + k];
            unsigned long long h3 = Hs[(ty * 4 + 3) * 16 + k];
            ulonglong2 w0 = *(const ulonglong2*)&Ws[k * 64 + tx * 8];
            ulonglong2 w1 = *(const ulonglong2*)&Ws[k * 64 + tx * 8 + 4];
            FMA2(acc[0][0], h0, w0.x); FMA2(acc[0][1], h0, w0.y);
            FMA2(acc[0][2], h0, w1.x); FMA2(acc[0][3], h0, w1.y);
            FMA2(acc[1][0], h1, w0.x); FMA2(acc[1][1], h1, w0.y);
            FMA2(acc[1][2], h1, w1.x); FMA2(acc[1][3], h1, w1.y);
            FMA2(acc[2][0], h2, w0.x); FMA2(acc[2][1], h2, w0.y);
            FMA2(acc[2][2], h2, w1.x); FMA2(acc[2][3], h2, w1.y);
            FMA2(acc[3][0], h3, w0.x); FMA2(acc[3][1], h3, w0.y);
            FMA2(acc[3][2], h3, w1.x); FMA2(acc[3][3], h3, w1.y);
        }
    }

    float bo[8];
#pragma unroll
    for (int c = 0; c < 8; c++) bo[c] = b_o[cb * 64 + tx * 8 + c];

#pragma unroll
    for (int i = 0; i < 4; i++) {
        int rr = rb * 128 + ty * 4 + i;     // flat index = s*256 + b
        int s = rr >> 8;
        int b = rr & 255;
        float* dst = out + ((size_t)b * S_ + s) * V_ + cb * 64 + tx * 8;
        float f[8];
        unpack2(acc[i][0], f[0], f[1]);
        unpack2(acc[i][1], f[2], f[3]);
        unpack2(acc[i][2], f[4], f[5]);
        unpack2(acc[i][3], f[6], f[7]);
        float4 o0 = make_float4(f[0] + bo[0], f[1] + bo[1], f[2] + bo[2], f[3] + bo[3]);
        float4 o1 = make_float4(f[4] + bo[4], f[5] + bo[5], f[6] + bo[6], f[7] + bo[7]);
        *(float4*)dst = o0;
        *((float4*)dst + 1) = o1;
    }
}

// ============================================================
// Kernel 4: hT = g_H[S-1]  (appended after outputs in d_out)
// ============================================================
__global__ void copy_hT(float* __restrict__ out) {
    int i = blockIdx.x * blockDim.x + threadIdx.x;   // 0 .. B_*H_-1
    out[(size_t)B_ * S_ * V_ + i] = g_H[(size_t)(S_ - 1) * (B_ * H_) + i];
}

// ============================================================
extern "C" void kernel_launch(void* const* d_in, const int* in_sizes, int n_in,
                              void* d_out, int out_size) {
    const int*   x    = (const int*)d_in[0];
    const float* emb  = (const float*)d_in[1];
    const float* W_ih = (const float*)d_in[2];
    const float* b_ih = (const float*)d_in[3];
    const float* W_hh = (const float*)d_in[4];
    const float* b_hh = (const float*)d_in[5];
    const float* W_ho = (const float*)d_in[6];
    const float* b_o  = (const float*)d_in[7];
    float* out = (float*)d_out;

    const int smem_bytes = 512 * 64 * 4 + 16 * HS_STRIDE * 8;   // 128KB + ~64KB
    static int attr_done = 0;
    if (!attr_done) {
        cudaFuncSetAttribute(rnn_persist, cudaFuncAttributeMaxDynamicSharedMemorySize, smem_bytes);
        attr_done = 1;
    }

    precompute_P<<<V_, H_>>>(emb, W_ih, b_ih, b_hh);

    rnn_persist<<<dim3(8, 16), 256, smem_bytes>>>(W_hh, x);

    out_gemm<<<dim3((B_ * S_) / 128, V_ / 64), 256>>>(W_ho, b_o, out);

    if ((long long)out_size >= (long long)B_ * S_ * V_ + (long long)B_ * H_)
        copy_hT<<<(B_ * H_) / 256, 256>>>(out);
}